// round 10
// baseline (speedup 1.0000x reference)
#include <cuda_runtime.h>
#include <cuda_fp16.h>
#include <cstdint>

// LuongAttention: O[b] = (Q Eᵀ) E == Q (EᵀE).  G = EᵀE per batch (128x128).
// fp16 split-precision 2-term products: x·y ≈ hi_x·(hi_y + lo_y) (err ~2e-4).
// R10: ete K=256/CTA in 4 pipelined stages (2-buffer smem), 64x64 output
// quarters (grid 256), partials down to 4 MB; qg 32-row tiles (grid 512) with
// d-half staging + 2-deep G prefetch.  B=8, T=2048, D=128.

#define BB 8
#define NSPLIT 8
#define RSTRIDE 272                 // plane row stride, bytes
#define PLANE_T (64 * RSTRIDE)      // 17408 B (hi or lo plane, 64 tokens)
#define STAGE_SZ (2 * PLANE_T)      // hi + lo planes per stage

__device__ float g_part[BB * NSPLIT * 128 * 128];   // 4 MB partials
// B-fragment layout: [b][n8tile 16][kstep 8][lane 32] = uint4
//   uint4 = { hi_b0, hi_b1, lo_b0, lo_b1 } (fp16x2 each).
__device__ uint4 g_frag[BB * 16 * 8 * 32];          // 512 KB

// ---------------- helpers ----------------
__device__ __forceinline__ uint32_t smem_u32(const void* p) {
    uint32_t a;
    asm("{ .reg .u64 t; cvta.to.shared.u64 t, %1; cvt.u32.u64 %0, t; }"
        : "=r"(a) : "l"(p));
    return a;
}
__device__ __forceinline__ void ldsm_x4(uint32_t (&r)[4], uint32_t addr) {
    asm volatile("ldmatrix.sync.aligned.m8n8.x4.shared.b16 {%0,%1,%2,%3}, [%4];"
                 : "=r"(r[0]), "=r"(r[1]), "=r"(r[2]), "=r"(r[3]) : "r"(addr));
}
__device__ __forceinline__ void ldsm_x4_t(uint32_t (&r)[4], uint32_t addr) {
    asm volatile("ldmatrix.sync.aligned.m8n8.x4.trans.shared.b16 {%0,%1,%2,%3}, [%4];"
                 : "=r"(r[0]), "=r"(r[1]), "=r"(r[2]), "=r"(r[3]) : "r"(addr));
}
__device__ __forceinline__ void mma16816(float (&d)[4], const uint32_t (&a)[4],
                                         uint32_t b0, uint32_t b1) {
    asm volatile(
        "mma.sync.aligned.m16n8k16.row.col.f32.f16.f16.f32 "
        "{%0,%1,%2,%3}, {%4,%5,%6,%7}, {%8,%9}, {%0,%1,%2,%3};"
        : "+f"(d[0]), "+f"(d[1]), "+f"(d[2]), "+f"(d[3])
        : "r"(a[0]), "r"(a[1]), "r"(a[2]), "r"(a[3]), "r"(b0), "r"(b1));
}
__device__ __forceinline__ void split2h(float f0, float f1, uint32_t& hi, uint32_t& lo) {
    __half2 h = __floats2half2_rn(f0, f1);
    float2 hf = __half22float2(h);
    __half2 l = __floats2half2_rn(f0 - hf.x, f1 - hf.y);
    hi = *(uint32_t*)&h;
    lo = *(uint32_t*)&l;
}
__device__ __forceinline__ uint32_t pack2h(float f0, float f1) {
    __half2 h = __floats2half2_rn(f0, f1);
    return *(uint32_t*)&h;
}

// Split+store one 64-token register batch into a stage's hi/lo planes.
__device__ __forceinline__ void stage_store(char* smem, int stage, int tid,
                                            const float4* q) {
    char* base = smem + stage * STAGE_SZ;
#pragma unroll
    for (int v = 0; v < 8; v++) {
        int idx = tid + v * 256;
        int t = idx >> 5, d4 = idx & 31;
        uint32_t h0, l0, h1, l1;
        split2h(q[v].x, q[v].y, h0, l0);
        split2h(q[v].z, q[v].w, h1, l1);
        uint32_t off = (uint32_t)t * RSTRIDE + (uint32_t)d4 * 8;
        *(uint2*)(base + off) = make_uint2(h0, h1);
        *(uint2*)(base + PLANE_T + off) = make_uint2(l0, l1);
    }
}

// MMA over one 64-token stage (4 ksteps), trans layout, 32x16 warp tile.
__device__ __forceinline__ void stage_mma64(uint32_t sbase, int wm, int wn, int lid,
                                            float (&acc)[2][2][4]) {
    const uint32_t aRow = (lid & 7) + ((lid >> 4) << 3);
    const uint32_t aCol = ((lid >> 3) & 1) << 3;
    const uint32_t bRow = (lid & 7) + (((lid >> 3) & 1) << 3);
    const uint32_t bCol = (lid >> 4) << 3;

#pragma unroll
    for (int kk = 0; kk < 4; kk++) {
        const int k0 = kk * 16;
        uint32_t Ah[2][4], Bh[4], Bl[4];
#pragma unroll
        for (int mi = 0; mi < 2; mi++) {
            uint32_t off = (uint32_t)(k0 + aRow) * RSTRIDE +
                           (uint32_t)(wm + mi * 16 + aCol) * 2;
            ldsm_x4_t(Ah[mi], sbase + off);
        }
        {
            uint32_t off = (uint32_t)(k0 + bRow) * RSTRIDE +
                           (uint32_t)(wn + bCol) * 2;
            ldsm_x4_t(Bh, sbase + off);
            ldsm_x4_t(Bl, sbase + PLANE_T + off);
        }
#pragma unroll
        for (int mi = 0; mi < 2; mi++)
#pragma unroll
            for (int nj = 0; nj < 2; nj++)
                mma16816(acc[mi][nj], Ah[mi], Bh[2 * nj], Bh[2 * nj + 1]);
#pragma unroll
        for (int mi = 0; mi < 2; mi++)
#pragma unroll
            for (int nj = 0; nj < 2; nj++)
                mma16816(acc[mi][nj], Ah[mi], Bl[2 * nj], Bl[2 * nj + 1]);
    }
}

// ---------------------------------------------------------------------------
// Kernel 1: partial EᵀE.  CTA: 64x64 quarter of G_sp, K = 256 tokens in four
// 64-token stages (2 smem buffers; stage s+1 LDG flies under stage s MMA).
// Grid (4*NSPLIT, BB); bx = sp*4 + mhalf*2 + nhalf.
// ---------------------------------------------------------------------------
__global__ __launch_bounds__(256) void ete_hmma(const float* __restrict__ enc) {
    extern __shared__ char smem[];
    const uint32_t sb = smem_u32(smem);
    const int tid = threadIdx.x, wid = tid >> 5, lid = tid & 31;
    const int sp = blockIdx.x >> 2;
    const int mhalf = (blockIdx.x >> 1) & 1, nhalf = blockIdx.x & 1;
    const int b = blockIdx.y;

    const float4* src =
        (const float4*)(enc + (size_t)(b * NSPLIT + sp) * (256 * 128));

    const int wm = mhalf * 64 + (wid >> 2) * 32;
    const int wn = nhalf * 64 + (wid & 3) * 16;
    float acc[2][2][4];
#pragma unroll
    for (int mi = 0; mi < 2; mi++)
#pragma unroll
        for (int nj = 0; nj < 2; nj++)
#pragma unroll
            for (int r = 0; r < 4; r++) acc[mi][nj][r] = 0.0f;

    float4 q[8];
#pragma unroll
    for (int v = 0; v < 8; v++) q[v] = src[tid + v * 256];
    stage_store(smem, 0, tid, q);
    __syncthreads();

#pragma unroll
    for (int s = 0; s < 4; s++) {
        if (s < 3) {                              // issue next-stage LDGs now
#pragma unroll
            for (int v = 0; v < 8; v++)
                q[v] = src[(s + 1) * 2048 + tid + v * 256];
        }
        stage_mma64(sb + (s & 1) * STAGE_SZ, wm, wn, lid, acc);
        if (s < 3) {
            stage_store(smem, (s + 1) & 1, tid, q);
            __syncthreads();
        }
    }

    // Epilogue: 64x64 tile into g_part[b][sp].
    float* outp = g_part + ((size_t)(b * NSPLIT + sp) << 14);
    const int g = lid >> 2, tig = lid & 3;
#pragma unroll
    for (int mi = 0; mi < 2; mi++)
#pragma unroll
        for (int nj = 0; nj < 2; nj++) {
            const int row = wm + mi * 16 + g;
            const int col = wn + nj * 8 + 2 * tig;
            *(float2*)(outp + row * 128 + col) =
                make_float2(acc[mi][nj][0], acc[mi][nj][1]);
            *(float2*)(outp + (row + 8) * 128 + col) =
                make_float2(acc[mi][nj][2], acc[mi][nj][3]);
        }
}

// ---------------------------------------------------------------------------
// Kernel 2: reduce 8 partials; emit G rows as fp16 mma B-fragments (hi+lo).
// ---------------------------------------------------------------------------
__global__ __launch_bounds__(256) void reduce_g() {
    const int e2 = blockIdx.x * 256 + threadIdx.x;  // 0..65535
    const int b = e2 >> 13;
    const int r = e2 & 8191;
    const int j = r >> 6, d2 = r & 63;
    const float2* base =
        (const float2*)(g_part + ((size_t)b << 17) + j * 128) + d2;
    float sx = 0.f, sy = 0.f;
#pragma unroll
    for (int sp = 0; sp < NSPLIT; sp++) {
        float2 v = base[(size_t)sp << 13];
        sx += v.x; sy += v.y;
    }
    uint32_t hi, lo;
    split2h(sx, sy, hi, lo);
    const uint32_t lane = (uint32_t)(j & 7) * 4 + (d2 & 3);
    const uint32_t comp = (uint32_t)(d2 >> 2) & 1;
    const uint32_t slot = (((uint32_t)(b * 16 + (j >> 3)) * 8 + (d2 >> 3)) * 32 + lane);
    uint32_t* f = (uint32_t*)g_frag + slot * 4;
    f[comp] = hi;
    f[comp + 2] = lo;
}

// ---------------------------------------------------------------------------
// Kernel 3: O_tile(32x128) = Qhi_tile @ (Ghi + Glo).  Grid (64, BB), occ 3.
// d-half staging: store d<64, sync, MMA k0-3 while storing d>=64.
// G fragments LDG.128 from gmem (L2-hot), 2-deep prefetch.
// ---------------------------------------------------------------------------
#define QG_SMEM (32 * RSTRIDE)      // 8704 B

__global__ __launch_bounds__(256, 3) void qg_hmma(const float* __restrict__ dec,
                                                  float* __restrict__ out) {
    extern __shared__ char smem[];
    const uint32_t sb = smem_u32(smem);
    const int tid = threadIdx.x, wid = tid >> 5, lid = tid & 31;
    const int b = blockIdx.y, qt = blockIdx.x;

    // Q tile [32 q][128 d], hi plane only; 4 float4 per thread.
    const float4* qsrc = (const float4*)(dec + ((size_t)(b * 64 + qt) << 12));
    float4 q[4];
#pragma unroll
    for (int v = 0; v < 4; v++) q[v] = qsrc[tid + v * 256];

    const bool s0 = (tid & 31) < 16;     // this thread's float4s are d<64

#define STORE_Q()                                                              \
    do {                                                                       \
        _Pragma("unroll") for (int v = 0; v < 4; v++) {                        \
            int idx = tid + v * 256;                                           \
            int row = idx >> 5, d4 = idx & 31;                                 \
            uint32_t off = (uint32_t)row * RSTRIDE + (uint32_t)d4 * 8;         \
            *(uint2*)(smem + off) =                                            \
                make_uint2(pack2h(q[v].x, q[v].y), pack2h(q[v].z, q[v].w));    \
        }                                                                      \
    } while (0)

    if (s0) STORE_Q();
    __syncthreads();

    const int wm = (wid >> 2) * 16, wn = (wid & 3) * 32;
    const uint4* gf = g_frag + ((size_t)(b * 16 + (wn >> 3)) * 8) * 32 + lid;

    float acc[4][4];
#pragma unroll
    for (int nj = 0; nj < 4; nj++)
#pragma unroll
        for (int r = 0; r < 4; r++) acc[nj][r] = 0.0f;

    const uint32_t aRow = lid & 15;
    const uint32_t aCol = (lid >> 4) << 3;

    // G fragments: double-buffer, 2-deep prefetch.
    uint4 Gb[2][4];
#pragma unroll
    for (int nj = 0; nj < 4; nj++) Gb[0][nj] = gf[nj * 256];
#pragma unroll
    for (int nj = 0; nj < 4; nj++) Gb[1][nj] = gf[nj * 256 + 32];

    if (!s0) STORE_Q();                   // d>=64 stores overlap ksteps 0-3

#pragma unroll
    for (int kk = 0; kk < 8; kk++) {
        if (kk == 4) __syncthreads();     // d>=64 plane ready
        const int k0 = kk * 16;
        const int buf = kk & 1;
        uint32_t Ah[4];
        {
            uint32_t off = (uint32_t)(wm + aRow) * RSTRIDE +
                           (uint32_t)(k0 + aCol) * 2;
            ldsm_x4(Ah, sb + off);
        }
#pragma unroll
        for (int nj = 0; nj < 4; nj++)
            mma16816(acc[nj], Ah, Gb[buf][nj].x, Gb[buf][nj].y);   // hiQ·hiG
#pragma unroll
        for (int nj = 0; nj < 4; nj++)
            mma16816(acc[nj], Ah, Gb[buf][nj].z, Gb[buf][nj].w);   // hiQ·loG
        if (kk < 6) {
#pragma unroll
            for (int nj = 0; nj < 4; nj++)
                Gb[buf][nj] = gf[nj * 256 + (kk + 2) * 32];
        }
    }

    float* outp = out + ((size_t)(b * 64 + qt) << 12);
    const int g = lid >> 2, tig = lid & 3;
#pragma unroll
    for (int nj = 0; nj < 4; nj++) {
        const int row = wm + g;
        const int col = wn + nj * 8 + 2 * tig;
        *(float2*)(outp + row * 128 + col) = make_float2(acc[nj][0], acc[nj][1]);
        *(float2*)(outp + (row + 8) * 128 + col) = make_float2(acc[nj][2], acc[nj][3]);
    }
#undef STORE_Q
}

// ---------------------------------------------------------------------------
// Launch
// ---------------------------------------------------------------------------
extern "C" void kernel_launch(void* const* d_in, const int* in_sizes, int n_in,
                              void* d_out, int out_size) {
    const float* enc = (const float*)d_in[0];
    const float* dec = (const float*)d_in[1];
    float* out = (float*)d_out;

    cudaFuncSetAttribute(ete_hmma, cudaFuncAttributeMaxDynamicSharedMemorySize,
                         2 * STAGE_SZ);
    cudaFuncSetAttribute(qg_hmma, cudaFuncAttributeMaxDynamicSharedMemorySize,
                         QG_SMEM);

    ete_hmma<<<dim3(4 * NSPLIT, BB), 256, 2 * STAGE_SZ>>>(enc);
    reduce_g<<<256, 256>>>();
    qg_hmma<<<dim3(64, BB), 256, QG_SMEM>>>(dec, out);
}

// round 11
// speedup vs baseline: 1.0921x; 1.0921x over previous
#include <cuda_runtime.h>
#include <cuda_fp16.h>
#include <cstdint>

// LuongAttention: O[b] = (Q Eᵀ) E == Q (EᵀE).  G = EᵀE per batch (128x128).
// fp16 split-precision 2-term products: x·y ≈ hi_x·(hi_y + lo_y) (err ~2e-4).
// R11: best measured combination — ete from R9 (K=128/CTA double-buffered,
// 8.96us), reduce over 16 partials, qg from R10 (32-row tiles, grid 512,
// d-half staging, ~6us).  B=8, T=2048, D=128.

#define BB 8
#define NSPLIT 16
#define RSTRIDE 272                 // plane row stride, bytes
#define PLANE_T (64 * RSTRIDE)      // 17408 B
#define STAGE_SZ (2 * PLANE_T)      // hi + lo planes per stage

__device__ float g_part[BB * NSPLIT * 128 * 128];   // 8 MB partials
// B-fragment layout: [b][n8tile 16][kstep 8][lane 32] = uint4
//   uint4 = { hi_b0, hi_b1, lo_b0, lo_b1 } (fp16x2 each).
__device__ uint4 g_frag[BB * 16 * 8 * 32];          // 512 KB

// ---------------- helpers ----------------
__device__ __forceinline__ uint32_t smem_u32(const void* p) {
    uint32_t a;
    asm("{ .reg .u64 t; cvta.to.shared.u64 t, %1; cvt.u32.u64 %0, t; }"
        : "=r"(a) : "l"(p));
    return a;
}
__device__ __forceinline__ void ldsm_x4(uint32_t (&r)[4], uint32_t addr) {
    asm volatile("ldmatrix.sync.aligned.m8n8.x4.shared.b16 {%0,%1,%2,%3}, [%4];"
                 : "=r"(r[0]), "=r"(r[1]), "=r"(r[2]), "=r"(r[3]) : "r"(addr));
}
__device__ __forceinline__ void ldsm_x4_t(uint32_t (&r)[4], uint32_t addr) {
    asm volatile("ldmatrix.sync.aligned.m8n8.x4.trans.shared.b16 {%0,%1,%2,%3}, [%4];"
                 : "=r"(r[0]), "=r"(r[1]), "=r"(r[2]), "=r"(r[3]) : "r"(addr));
}
__device__ __forceinline__ void mma16816(float (&d)[4], const uint32_t (&a)[4],
                                         uint32_t b0, uint32_t b1) {
    asm volatile(
        "mma.sync.aligned.m16n8k16.row.col.f32.f16.f16.f32 "
        "{%0,%1,%2,%3}, {%4,%5,%6,%7}, {%8,%9}, {%0,%1,%2,%3};"
        : "+f"(d[0]), "+f"(d[1]), "+f"(d[2]), "+f"(d[3])
        : "r"(a[0]), "r"(a[1]), "r"(a[2]), "r"(a[3]), "r"(b0), "r"(b1));
}
__device__ __forceinline__ void split2h(float f0, float f1, uint32_t& hi, uint32_t& lo) {
    __half2 h = __floats2half2_rn(f0, f1);
    float2 hf = __half22float2(h);
    __half2 l = __floats2half2_rn(f0 - hf.x, f1 - hf.y);
    hi = *(uint32_t*)&h;
    lo = *(uint32_t*)&l;
}
__device__ __forceinline__ uint32_t pack2h(float f0, float f1) {
    __half2 h = __floats2half2_rn(f0, f1);
    return *(uint32_t*)&h;
}

__device__ __forceinline__ void warp_epilogue32(float* outp, int wm, int wn, int lid,
                                                float (&acc)[2][4][4]) {
    const int g = lid >> 2, tig = lid & 3;
#pragma unroll
    for (int mi = 0; mi < 2; mi++)
#pragma unroll
        for (int nj = 0; nj < 4; nj++) {
            const int row = wm + mi * 16 + g;
            const int col = wn + nj * 8 + 2 * tig;
            *(float2*)(outp + row * 128 + col) =
                make_float2(acc[mi][nj][0], acc[mi][nj][1]);
            *(float2*)(outp + (row + 8) * 128 + col) =
                make_float2(acc[mi][nj][2], acc[mi][nj][3]);
        }
}

// Split+store one 64-token register batch into a stage's hi/lo planes.
__device__ __forceinline__ void stage_store(char* smem, int stage, int tid,
                                            const float4* q) {
    char* base = smem + stage * STAGE_SZ;
#pragma unroll
    for (int v = 0; v < 8; v++) {
        int idx = tid + v * 256;
        int t = idx >> 5, d4 = idx & 31;
        uint32_t h0, l0, h1, l1;
        split2h(q[v].x, q[v].y, h0, l0);
        split2h(q[v].z, q[v].w, h1, l1);
        uint32_t off = (uint32_t)t * RSTRIDE + (uint32_t)d4 * 8;
        *(uint2*)(base + off) = make_uint2(h0, h1);
        *(uint2*)(base + PLANE_T + off) = make_uint2(l0, l1);
    }
}

// MMA over one 64-token stage (4 ksteps), trans layout, 32x32 warp tile.
__device__ __forceinline__ void stage_mma(uint32_t sbase, int wm, int wn, int lid,
                                          float (&acc)[2][4][4]) {
    const uint32_t aRow = (lid & 7) + ((lid >> 4) << 3);
    const uint32_t aCol = ((lid >> 3) & 1) << 3;
    const uint32_t bRow = (lid & 7) + (((lid >> 3) & 1) << 3);
    const uint32_t bCol = (lid >> 4) << 3;

#pragma unroll
    for (int kk = 0; kk < 4; kk++) {
        const int k0 = kk * 16;
        uint32_t Ah[2][4], Bh[2][4], Bl[2][4];
#pragma unroll
        for (int mi = 0; mi < 2; mi++) {
            uint32_t off = (uint32_t)(k0 + aRow) * RSTRIDE +
                           (uint32_t)(wm + mi * 16 + aCol) * 2;
            ldsm_x4_t(Ah[mi], sbase + off);
        }
#pragma unroll
        for (int np = 0; np < 2; np++) {
            uint32_t off = (uint32_t)(k0 + bRow) * RSTRIDE +
                           (uint32_t)(wn + np * 16 + bCol) * 2;
            ldsm_x4_t(Bh[np], sbase + off);
            ldsm_x4_t(Bl[np], sbase + PLANE_T + off);
        }
#pragma unroll
        for (int mi = 0; mi < 2; mi++)
#pragma unroll
            for (int nj = 0; nj < 4; nj++) {
                const int np = nj >> 1, pr = (nj & 1) << 1;
                mma16816(acc[mi][nj], Ah[mi], Bh[np][pr], Bh[np][pr + 1]);
            }
#pragma unroll
        for (int mi = 0; mi < 2; mi++)
#pragma unroll
            for (int nj = 0; nj < 4; nj++) {
                const int np = nj >> 1, pr = (nj & 1) << 1;
                mma16816(acc[mi][nj], Ah[mi], Bl[np][pr], Bl[np][pr + 1]);
            }
    }
}

// ---------------------------------------------------------------------------
// Kernel 1 (R9): partial EᵀE.  CTA (sp, half): K = 128 tokens in two
// 64-token stages, double-buffered; stage-1 LDG overlaps stage-0 MMA.
// Grid (2*NSPLIT, BB); bx = sp*2 + half.
// ---------------------------------------------------------------------------
__global__ __launch_bounds__(256) void ete_hmma(const float* __restrict__ enc) {
    extern __shared__ char smem[];
    const uint32_t sb = smem_u32(smem);
    const int tid = threadIdx.x, wid = tid >> 5, lid = tid & 31;
    const int sp = blockIdx.x >> 1, half = blockIdx.x & 1, b = blockIdx.y;

    const float4* src =
        (const float4*)(enc + (size_t)(b * NSPLIT + sp) * (128 * 128));

    float4 q0[8];
#pragma unroll
    for (int v = 0; v < 8; v++) q0[v] = src[tid + v * 256];
    stage_store(smem, 0, tid, q0);
    __syncthreads();

    // Stage 1 loads issued NOW — they fly while stage-0 MMAs run.
    float4 q1[8];
#pragma unroll
    for (int v = 0; v < 8; v++) q1[v] = src[2048 + tid + v * 256];

    const int wm = half * 64 + (wid >> 2) * 32, wn = (wid & 3) * 32;
    float acc[2][4][4];
#pragma unroll
    for (int mi = 0; mi < 2; mi++)
#pragma unroll
        for (int nj = 0; nj < 4; nj++)
#pragma unroll
            for (int r = 0; r < 4; r++) acc[mi][nj][r] = 0.0f;

    stage_mma(sb, wm, wn, lid, acc);            // tokens 0..63

    stage_store(smem, 1, tid, q1);
    __syncthreads();

    stage_mma(sb + STAGE_SZ, wm, wn, lid, acc); // tokens 64..127

    warp_epilogue32(g_part + ((size_t)(b * NSPLIT + sp) << 14), wm, wn, lid, acc);
}

// ---------------------------------------------------------------------------
// Kernel 2: reduce 16 partials; emit G rows as fp16 mma B-fragments (hi+lo).
// ---------------------------------------------------------------------------
__global__ __launch_bounds__(256) void reduce_g() {
    const int e2 = blockIdx.x * 256 + threadIdx.x;  // 0..65535
    const int b = e2 >> 13;
    const int r = e2 & 8191;
    const int j = r >> 6, d2 = r & 63;
    const float2* base =
        (const float2*)(g_part + ((size_t)b << 18) + j * 128) + d2;
    float sx = 0.f, sy = 0.f;
#pragma unroll
    for (int sp = 0; sp < NSPLIT; sp++) {
        float2 v = base[(size_t)sp << 13];
        sx += v.x; sy += v.y;
    }
    uint32_t hi, lo;
    split2h(sx, sy, hi, lo);
    const uint32_t lane = (uint32_t)(j & 7) * 4 + (d2 & 3);
    const uint32_t comp = (uint32_t)(d2 >> 2) & 1;
    const uint32_t slot = (((uint32_t)(b * 16 + (j >> 3)) * 8 + (d2 >> 3)) * 32 + lane);
    uint32_t* f = (uint32_t*)g_frag + slot * 4;
    f[comp] = hi;
    f[comp + 2] = lo;
}

// ---------------------------------------------------------------------------
// Kernel 3 (R10): O_tile(32x128) = Qhi_tile @ (Ghi + Glo).  Grid (64, BB),
// occ 3, d-half staging, 2-deep G-fragment prefetch from gmem (L2-hot).
// ---------------------------------------------------------------------------
#define QG_SMEM (32 * RSTRIDE)      // 8704 B

__global__ __launch_bounds__(256, 3) void qg_hmma(const float* __restrict__ dec,
                                                  float* __restrict__ out) {
    extern __shared__ char smem[];
    const uint32_t sb = smem_u32(smem);
    const int tid = threadIdx.x, wid = tid >> 5, lid = tid & 31;
    const int b = blockIdx.y, qt = blockIdx.x;

    // Q tile [32 q][128 d], hi plane only; 4 float4 per thread.
    const float4* qsrc = (const float4*)(dec + ((size_t)(b * 64 + qt) << 12));
    float4 q[4];
#pragma unroll
    for (int v = 0; v < 4; v++) q[v] = qsrc[tid + v * 256];

    const bool s0 = (tid & 31) < 16;     // this thread's float4s are d<64

#define STORE_Q()                                                              \
    do {                                                                       \
        _Pragma("unroll") for (int v = 0; v < 4; v++) {                        \
            int idx = tid + v * 256;                                           \
            int row = idx >> 5, d4 = idx & 31;                                 \
            uint32_t off = (uint32_t)row * RSTRIDE + (uint32_t)d4 * 8;         \
            *(uint2*)(smem + off) =                                            \
                make_uint2(pack2h(q[v].x, q[v].y), pack2h(q[v].z, q[v].w));    \
        }                                                                      \
    } while (0)

    if (s0) STORE_Q();
    __syncthreads();

    const int wm = (wid >> 2) * 16, wn = (wid & 3) * 32;
    const uint4* gf = g_frag + ((size_t)(b * 16 + (wn >> 3)) * 8) * 32 + lid;

    float acc[4][4];
#pragma unroll
    for (int nj = 0; nj < 4; nj++)
#pragma unroll
        for (int r = 0; r < 4; r++) acc[nj][r] = 0.0f;

    const uint32_t aRow = lid & 15;
    const uint32_t aCol = (lid >> 4) << 3;

    uint4 Gb[2][4];
#pragma unroll
    for (int nj = 0; nj < 4; nj++) Gb[0][nj] = gf[nj * 256];
#pragma unroll
    for (int nj = 0; nj < 4; nj++) Gb[1][nj] = gf[nj * 256 + 32];

    if (!s0) STORE_Q();                   // d>=64 stores overlap ksteps 0-3

#pragma unroll
    for (int kk = 0; kk < 8; kk++) {
        if (kk == 4) __syncthreads();     // d>=64 plane ready
        const int k0 = kk * 16;
        const int buf = kk & 1;
        uint32_t Ah[4];
        {
            uint32_t off = (uint32_t)(wm + aRow) * RSTRIDE +
                           (uint32_t)(k0 + aCol) * 2;
            ldsm_x4(Ah, sb + off);
        }
#pragma unroll
        for (int nj = 0; nj < 4; nj++)
            mma16816(acc[nj], Ah, Gb[buf][nj].x, Gb[buf][nj].y);   // hiQ·hiG
#pragma unroll
        for (int nj = 0; nj < 4; nj++)
            mma16816(acc[nj], Ah, Gb[buf][nj].z, Gb[buf][nj].w);   // hiQ·loG
        if (kk < 6) {
#pragma unroll
            for (int nj = 0; nj < 4; nj++)
                Gb[buf][nj] = gf[nj * 256 + (kk + 2) * 32];
        }
    }

    float* outp = out + ((size_t)(b * 64 + qt) << 12);
    const int g = lid >> 2, tig = lid & 3;
#pragma unroll
    for (int nj = 0; nj < 4; nj++) {
        const int row = wm + g;
        const int col = wn + nj * 8 + 2 * tig;
        *(float2*)(outp + row * 128 + col) = make_float2(acc[nj][0], acc[nj][1]);
        *(float2*)(outp + (row + 8) * 128 + col) = make_float2(acc[nj][2], acc[nj][3]);
    }
#undef STORE_Q
}

// ---------------------------------------------------------------------------
// Launch
// ---------------------------------------------------------------------------
extern "C" void kernel_launch(void* const* d_in, const int* in_sizes, int n_in,
                              void* d_out, int out_size) {
    const float* enc = (const float*)d_in[0];
    const float* dec = (const float*)d_in[1];
    float* out = (float*)d_out;

    cudaFuncSetAttribute(ete_hmma, cudaFuncAttributeMaxDynamicSharedMemorySize,
                         2 * STAGE_SZ);
    cudaFuncSetAttribute(qg_hmma, cudaFuncAttributeMaxDynamicSharedMemorySize,
                         QG_SMEM);

    ete_hmma<<<dim3(2 * NSPLIT, BB), 256, 2 * STAGE_SZ>>>(enc);
    reduce_g<<<256, 256>>>();
    qg_hmma<<<dim3(64, BB), 256, QG_SMEM>>>(dec, out);
}

// round 12
// speedup vs baseline: 1.1235x; 1.0288x over previous
#include <cuda_runtime.h>
#include <cuda_fp16.h>
#include <cstdint>

// LuongAttention: O[b] = (Q Eᵀ) E == Q (EᵀE).  G = EᵀE per batch (128x128).
// fp16 split-precision 2-term products: x·y ≈ hi_x·(hi_y + lo_y) (err ~2e-4).
// R12: ete exploits G symmetry — per split-chunk, 3 CTAs compute blocks
// (0,0), (0,1), (1,1) of the symmetric partial; the (1,0) tile is mirrored
// via an smem transpose.  25% fewer MMAs, same LDG.  qg = R9 (best measured).

#define BB 8
#define NSPLIT 16
#define RSTRIDE 272                 // plane row stride, bytes
#define PLANE_T (64 * RSTRIDE)      // 17408 B
#define STAGE_SZ (2 * PLANE_T)      // hi + lo planes per stage

__device__ float g_part[BB * NSPLIT * 128 * 128];   // 8 MB partials
// B-fragment layout: [b][n8tile 16][kstep 8][lane 32] = uint4
//   uint4 = { hi_b0, hi_b1, lo_b0, lo_b1 } (fp16x2 each).
__device__ uint4 g_frag[BB * 16 * 8 * 32];          // 512 KB

// ---------------- helpers ----------------
__device__ __forceinline__ uint32_t smem_u32(const void* p) {
    uint32_t a;
    asm("{ .reg .u64 t; cvta.to.shared.u64 t, %1; cvt.u32.u64 %0, t; }"
        : "=r"(a) : "l"(p));
    return a;
}
__device__ __forceinline__ void ldsm_x4(uint32_t (&r)[4], uint32_t addr) {
    asm volatile("ldmatrix.sync.aligned.m8n8.x4.shared.b16 {%0,%1,%2,%3}, [%4];"
                 : "=r"(r[0]), "=r"(r[1]), "=r"(r[2]), "=r"(r[3]) : "r"(addr));
}
__device__ __forceinline__ void ldsm_x4_t(uint32_t (&r)[4], uint32_t addr) {
    asm volatile("ldmatrix.sync.aligned.m8n8.x4.trans.shared.b16 {%0,%1,%2,%3}, [%4];"
                 : "=r"(r[0]), "=r"(r[1]), "=r"(r[2]), "=r"(r[3]) : "r"(addr));
}
__device__ __forceinline__ void mma16816(float (&d)[4], const uint32_t (&a)[4],
                                         uint32_t b0, uint32_t b1) {
    asm volatile(
        "mma.sync.aligned.m16n8k16.row.col.f32.f16.f16.f32 "
        "{%0,%1,%2,%3}, {%4,%5,%6,%7}, {%8,%9}, {%0,%1,%2,%3};"
        : "+f"(d[0]), "+f"(d[1]), "+f"(d[2]), "+f"(d[3])
        : "r"(a[0]), "r"(a[1]), "r"(a[2]), "r"(a[3]), "r"(b0), "r"(b1));
}
__device__ __forceinline__ void split2h(float f0, float f1, uint32_t& hi, uint32_t& lo) {
    __half2 h = __floats2half2_rn(f0, f1);
    float2 hf = __half22float2(h);
    __half2 l = __floats2half2_rn(f0 - hf.x, f1 - hf.y);
    hi = *(uint32_t*)&h;
    lo = *(uint32_t*)&l;
}
__device__ __forceinline__ uint32_t pack2h(float f0, float f1) {
    __half2 h = __floats2half2_rn(f0, f1);
    return *(uint32_t*)&h;
}

// MMA over one 64-token stage (4 ksteps), trans layout, 32x16 warp tile.
__device__ __forceinline__ void stage_mma64(uint32_t sbase, int wm, int wn, int lid,
                                            float (&acc)[2][2][4]) {
    const uint32_t aRow = (lid & 7) + ((lid >> 4) << 3);
    const uint32_t aCol = ((lid >> 3) & 1) << 3;
    const uint32_t bRow = (lid & 7) + (((lid >> 3) & 1) << 3);
    const uint32_t bCol = (lid >> 4) << 3;

#pragma unroll
    for (int kk = 0; kk < 4; kk++) {
        const int k0 = kk * 16;
        uint32_t Ah[2][4], Bh[4], Bl[4];
#pragma unroll
        for (int mi = 0; mi < 2; mi++) {
            uint32_t off = (uint32_t)(k0 + aRow) * RSTRIDE +
                           (uint32_t)(wm + mi * 16 + aCol) * 2;
            ldsm_x4_t(Ah[mi], sbase + off);
        }
        {
            uint32_t off = (uint32_t)(k0 + bRow) * RSTRIDE +
                           (uint32_t)(wn + bCol) * 2;
            ldsm_x4_t(Bh, sbase + off);
            ldsm_x4_t(Bl, sbase + PLANE_T + off);
        }
#pragma unroll
        for (int mi = 0; mi < 2; mi++)
#pragma unroll
            for (int nj = 0; nj < 2; nj++)
                mma16816(acc[mi][nj], Ah[mi], Bh[2 * nj], Bh[2 * nj + 1]);
#pragma unroll
        for (int mi = 0; mi < 2; mi++)
#pragma unroll
            for (int nj = 0; nj < 2; nj++)
                mma16816(acc[mi][nj], Ah[mi], Bl[2 * nj], Bl[2 * nj + 1]);
    }
}

// ---------------------------------------------------------------------------
// Kernel 1: partial EᵀE, triangle blocks.  Grid (3*NSPLIT, BB).
// btype 0 -> block (0,0), 1 -> (0,1) (+mirror to (1,0)), 2 -> (1,1).
// Diagonal blocks load only their 64 d-columns.  K = 128 tokens in two
// double-buffered 64-token stages (stage-1 LDG flies under stage-0 MMA).
// ---------------------------------------------------------------------------
__global__ __launch_bounds__(256, 2) void ete_hmma(const float* __restrict__ enc) {
    extern __shared__ char smem[];
    const uint32_t sb = smem_u32(smem);
    const int tid = threadIdx.x, wid = tid >> 5, lid = tid & 31;
    const int btype = blockIdx.x % 3, sp = blockIdx.x / 3, b = blockIdx.y;
    const int mh = (btype == 2), nh = (btype >= 1);
    const bool full = (btype == 1);

    // float4 view of this chunk (32 float4 per token row).
    const float4* src =
        (const float4*)(enc + (size_t)(b * NSPLIT + sp) * (128 * 128));

    // ---- stage load (to regs) + split/store helpers ----
    float4 q[8];
#define LOAD_STAGE(s)                                                          \
    do {                                                                       \
        if (full) {                                                            \
            _Pragma("unroll") for (int v = 0; v < 8; v++)                      \
                q[v] = src[(s) * 2048 + tid + v * 256];                        \
        } else {                                                               \
            _Pragma("unroll") for (int v = 0; v < 4; v++) {                    \
                int idx = tid + v * 256;                                       \
                int t = idx >> 4, d4 = (idx & 15) + mh * 16;                   \
                q[v] = src[(s) * 2048 + t * 32 + d4];                          \
            }                                                                  \
        }                                                                      \
    } while (0)
#define STORE_STAGE(st)                                                        \
    do {                                                                       \
        char* base = smem + (st) * STAGE_SZ;                                   \
        if (full) {                                                            \
            _Pragma("unroll") for (int v = 0; v < 8; v++) {                    \
                int idx = tid + v * 256;                                       \
                int t = idx >> 5, d4 = idx & 31;                               \
                uint32_t h0, l0, h1, l1;                                       \
                split2h(q[v].x, q[v].y, h0, l0);                               \
                split2h(q[v].z, q[v].w, h1, l1);                               \
                uint32_t off = (uint32_t)t * RSTRIDE + (uint32_t)d4 * 8;       \
                *(uint2*)(base + off) = make_uint2(h0, h1);                    \
                *(uint2*)(base + PLANE_T + off) = make_uint2(l0, l1);          \
            }                                                                  \
        } else {                                                               \
            _Pragma("unroll") for (int v = 0; v < 4; v++) {                    \
                int idx = tid + v * 256;                                       \
                int t = idx >> 4, d4 = (idx & 15) + mh * 16;                   \
                uint32_t h0, l0, h1, l1;                                       \
                split2h(q[v].x, q[v].y, h0, l0);                               \
                split2h(q[v].z, q[v].w, h1, l1);                               \
                uint32_t off = (uint32_t)t * RSTRIDE + (uint32_t)d4 * 8;       \
                *(uint2*)(base + off) = make_uint2(h0, h1);                    \
                *(uint2*)(base + PLANE_T + off) = make_uint2(l0, l1);          \
            }                                                                  \
        }                                                                      \
    } while (0)

    LOAD_STAGE(0);
    STORE_STAGE(0);
    __syncthreads();

    LOAD_STAGE(1);                        // flies under stage-0 MMAs

    const int wm = mh * 64 + (wid >> 2) * 32;
    const int wn = nh * 64 + (wid & 3) * 16;
    float acc[2][2][4];
#pragma unroll
    for (int mi = 0; mi < 2; mi++)
#pragma unroll
        for (int nj = 0; nj < 2; nj++)
#pragma unroll
            for (int r = 0; r < 4; r++) acc[mi][nj][r] = 0.0f;

    stage_mma64(sb, wm, wn, lid, acc);            // tokens 0..63

    STORE_STAGE(1);
    __syncthreads();

    stage_mma64(sb + STAGE_SZ, wm, wn, lid, acc); // tokens 64..127

    // ---- epilogue: write own tile ----
    float* outp = g_part + ((size_t)(b * NSPLIT + sp) << 14);
    const int g = lid >> 2, tig = lid & 3;
#pragma unroll
    for (int mi = 0; mi < 2; mi++)
#pragma unroll
        for (int nj = 0; nj < 2; nj++) {
            const int row = wm + mi * 16 + g;
            const int col = wn + nj * 8 + 2 * tig;
            *(float2*)(outp + row * 128 + col) =
                make_float2(acc[mi][nj][0], acc[mi][nj][1]);
            *(float2*)(outp + (row + 8) * 128 + col) =
                make_float2(acc[mi][nj][2], acc[mi][nj][3]);
        }

    // ---- (0,1) also writes the mirrored (1,0) tile via smem transpose ----
    if (full) {
        float* Tbuf = (float*)smem;       // aliases stage-0 planes (dead now)
        // Need: all warps past their stage-0 reads — guaranteed by the
        // mid-kernel __syncthreads(); all warps done with Tbuf region writes
        // require a sync before transposed reads.
#pragma unroll
        for (int mi = 0; mi < 2; mi++)
#pragma unroll
            for (int nj = 0; nj < 2; nj++) {
                const int lm = (wid >> 2) * 32 + mi * 16 + g;
                const int ln = (wid & 3) * 16 + nj * 8 + 2 * tig;
                Tbuf[lm * 65 + ln]       = acc[mi][nj][0];
                Tbuf[lm * 65 + ln + 1]   = acc[mi][nj][1];
                Tbuf[(lm + 8) * 65 + ln]     = acc[mi][nj][2];
                Tbuf[(lm + 8) * 65 + ln + 1] = acc[mi][nj][3];
            }
        __syncthreads();
        // Mirror: out[(64+i)][j] = tile(j, i).  Thread: row i = tid&63,
        // col chunk = tid>>6 (16 cols each).
        const int i = tid & 63, cg = (tid >> 6) * 16;
        float v[16];
#pragma unroll
        for (int jj = 0; jj < 16; jj++) v[jj] = Tbuf[(cg + jj) * 65 + i];
        float* mrow = outp + (64 + i) * 128 + cg;
#pragma unroll
        for (int jj = 0; jj < 16; jj += 4)
            *(float4*)(mrow + jj) = make_float4(v[jj], v[jj+1], v[jj+2], v[jj+3]);
    }
#undef LOAD_STAGE
#undef STORE_STAGE
}

// ---------------------------------------------------------------------------
// Kernel 2: reduce 16 partials; emit G rows as fp16 mma B-fragments (hi+lo).
// ---------------------------------------------------------------------------
__global__ __launch_bounds__(256) void reduce_g() {
    const int e2 = blockIdx.x * 256 + threadIdx.x;  // 0..65535
    const int b = e2 >> 13;
    const int r = e2 & 8191;
    const int j = r >> 6, d2 = r & 63;
    const float2* base =
        (const float2*)(g_part + ((size_t)b << 18) + j * 128) + d2;
    float sx = 0.f, sy = 0.f;
#pragma unroll
    for (int sp = 0; sp < NSPLIT; sp++) {
        float2 v = base[(size_t)sp << 13];
        sx += v.x; sy += v.y;
    }
    uint32_t hi, lo;
    split2h(sx, sy, hi, lo);
    const uint32_t lane = (uint32_t)(j & 7) * 4 + (d2 & 3);
    const uint32_t comp = (uint32_t)(d2 >> 2) & 1;
    const uint32_t slot = (((uint32_t)(b * 16 + (j >> 3)) * 8 + (d2 >> 3)) * 32 + lane);
    uint32_t* f = (uint32_t*)g_frag + slot * 4;
    f[comp] = hi;
    f[comp + 2] = lo;
}

// ---------------------------------------------------------------------------
// Kernel 3 (R9, best measured): O_tile(64x128) = Qhi_tile @ (Ghi + Glo).
// Q hi plane in smem; G fragments LDG.128 from gmem, 2-deep prefetch.
// ---------------------------------------------------------------------------
__global__ __launch_bounds__(256, 3) void qg_hmma(const float* __restrict__ dec,
                                                  float* __restrict__ out) {
    extern __shared__ char smem[];
    const uint32_t sb = smem_u32(smem);
    const int tid = threadIdx.x, wid = tid >> 5, lid = tid & 31;
    const int b = blockIdx.y, qt = blockIdx.x;

    const float4* qsrc = (const float4*)(dec + ((size_t)(b * 32 + qt) << 13));
    float4 q[8];
#pragma unroll
    for (int v = 0; v < 8; v++) q[v] = qsrc[tid + v * 256];
#pragma unroll
    for (int v = 0; v < 8; v++) {
        int idx = tid + v * 256;
        int row = idx >> 5, d4 = idx & 31;
        uint32_t off = (uint32_t)row * RSTRIDE + (uint32_t)d4 * 8;
        *(uint2*)(smem + off) =
            make_uint2(pack2h(q[v].x, q[v].y), pack2h(q[v].z, q[v].w));
    }
    __syncthreads();

    const int wm = (wid >> 2) * 32, wn = (wid & 3) * 32;
    const uint4* gf = g_frag + ((size_t)(b * 16 + (wn >> 3)) * 8) * 32 + lid;

    float acc[2][4][4];
#pragma unroll
    for (int mi = 0; mi < 2; mi++)
#pragma unroll
        for (int nj = 0; nj < 4; nj++)
#pragma unroll
            for (int r = 0; r < 4; r++) acc[mi][nj][r] = 0.0f;

    const uint32_t aRow = lid & 15;
    const uint32_t aCol = (lid >> 4) << 3;

    uint4 Gb[2][4];
#pragma unroll
    for (int nj = 0; nj < 4; nj++) Gb[0][nj] = gf[nj * 256];
#pragma unroll
    for (int nj = 0; nj < 4; nj++) Gb[1][nj] = gf[nj * 256 + 32];

#pragma unroll
    for (int kk = 0; kk < 8; kk++) {
        const int k0 = kk * 16;
        const int buf = kk & 1;
        uint32_t Ah[2][4];
#pragma unroll
        for (int mi = 0; mi < 2; mi++) {
            uint32_t off = (uint32_t)(wm + mi * 16 + aRow) * RSTRIDE +
                           (uint32_t)(k0 + aCol) * 2;
            ldsm_x4(Ah[mi], sb + off);
        }
#pragma unroll
        for (int mi = 0; mi < 2; mi++)
#pragma unroll
            for (int nj = 0; nj < 4; nj++)
                mma16816(acc[mi][nj], Ah[mi], Gb[buf][nj].x, Gb[buf][nj].y);
#pragma unroll
        for (int mi = 0; mi < 2; mi++)
#pragma unroll
            for (int nj = 0; nj < 4; nj++)
                mma16816(acc[mi][nj], Ah[mi], Gb[buf][nj].z, Gb[buf][nj].w);
        if (kk < 6) {
#pragma unroll
            for (int nj = 0; nj < 4; nj++)
                Gb[buf][nj] = gf[nj * 256 + (kk + 2) * 32];
        }
    }

    float* outp = out + ((size_t)(b * 32 + qt) << 13);
    const int g = lid >> 2, tig = lid & 3;
#pragma unroll
    for (int mi = 0; mi < 2; mi++)
#pragma unroll
        for (int nj = 0; nj < 4; nj++) {
            const int row = wm + mi * 16 + g;
            const int col = wn + nj * 8 + 2 * tig;
            *(float2*)(outp + row * 128 + col) =
                make_float2(acc[mi][nj][0], acc[mi][nj][1]);
            *(float2*)(outp + (row + 8) * 128 + col) =
                make_float2(acc[mi][nj][2], acc[mi][nj][3]);
        }
}

// ---------------------------------------------------------------------------
// Launch
// ---------------------------------------------------------------------------
extern "C" void kernel_launch(void* const* d_in, const int* in_sizes, int n_in,
                              void* d_out, int out_size) {
    const float* enc = (const float*)d_in[0];
    const float* dec = (const float*)d_in[1];
    float* out = (float*)d_out;

    cudaFuncSetAttribute(ete_hmma, cudaFuncAttributeMaxDynamicSharedMemorySize,
                         2 * STAGE_SZ);
    cudaFuncSetAttribute(qg_hmma, cudaFuncAttributeMaxDynamicSharedMemorySize,
                         PLANE_T);

    ete_hmma<<<dim3(3 * NSPLIT, BB), 256, 2 * STAGE_SZ>>>(enc);
    reduce_g<<<256, 256>>>();
    qg_hmma<<<dim3(32, BB), 256, PLANE_T>>>(dec, out);
}